// round 7
// baseline (speedup 1.0000x reference)
#include <cuda_runtime.h>

#define NJ    24
#define BATCH 500000
#define PAIRS (BATCH/2)
#define TPB   256
#define WPJ   104              // u64 pairs per joint: 13 row-chunks x 8 {bias,w0..w6}
#define SW_N  (NJ*WPJ)         // 2496 pairs = 19968 B static smem

typedef unsigned long long u64;

static __device__ __forceinline__ u64 pk2(float a, float b) {
    u64 r; asm("mov.b64 %0, {%1,%2};" : "=l"(r) : "f"(a), "f"(b)); return r;
}
static __device__ __forceinline__ void upk2(u64 v, float& a, float& b) {
    asm("mov.b64 {%0,%1}, %2;" : "=f"(a), "=f"(b) : "l"(v));
}
// Packed dual FMA on the Blackwell f32x2 pipe.
static __device__ __forceinline__ u64 ffma2(u64 a, u64 b, u64 c) {
    u64 d; asm("fma.rn.f32x2 %0, %1, %2, %3;" : "=l"(d) : "l"(a), "l"(b), "l"(c)); return d;
}
static __device__ __forceinline__ u64 relu2(u64 v) {
    float a, b; upk2(v, a, b);          // reg-pair rename, no instructions
    return pk2(fmaxf(a, 0.f), fmaxf(b, 0.f));
}

__global__ __launch_bounds__(TPB, 2)
void se1d_kernel(const float* __restrict__ x,
                 const float* __restrict__ W1, const float* __restrict__ b1,
                 const float* __restrict__ W2, const float* __restrict__ b2,
                 float* __restrict__ out)
{
    // Weights in static shared, duplicated {w,w} pairs.
    // Per joint j: 13 row-chunks of 8 pairs, each chunk 64B-aligned:
    //   chunks 0..6 :  {b1[r],   W1[r][0..6]}
    //   chunks 7..12:  {b2[r-7], W2[r-7][0..6]}
    __shared__ u64 sw[SW_N];
    for (int idx = threadIdx.x; idx < SW_N; idx += TPB) {
        int j = idx / WPJ, o = idx - j * WPJ;
        int row = o >> 3, s = o & 7;
        float v;
        if (row < 7) v = (s == 0) ? b1[j*7 + row]     : W1[j*49 + row*7     + (s-1)];
        else         v = (s == 0) ? b2[j*6 + (row-7)] : W2[j*42 + (row-7)*7 + (s-1)];
        sw[idx] = pk2(v, v);
    }
    __syncthreads();

    const int pair = blockIdx.x * TPB + threadIdx.x;
    if (pair >= PAIRS) return;

    const float4* xr0 = (const float4*)(x + (long)pair * 48);  // row 2t
    const float4* xr1 = xr0 + 6;                               // row 2t+1
    float* o0 = out + (long)pair * 288;
    float* o1 = o0 + 144;

    u64 xp[4];             // JIT x chunk: 4 joints at a time
    u64 feat[NJ][6];       // literal indices only -> SROA'd, max ~3 joints live
    float s0[12], s1[12];  // 2-joint output staging

// Load x chunk q: covers joints 4q..4q+3 (all literal).
#define LOADX(q) do { \
    float4 a_ = xr0[q], b_ = xr1[q]; \
    xp[0] = pk2(a_.x, b_.x); xp[1] = pk2(a_.y, b_.y); \
    xp[2] = pk2(a_.z, b_.z); xp[3] = pk2(a_.w, b_.w); \
} while (0)

// Layer-1 row r for joint j with parent p. Weights via LDS.128 (ulonglong2).
// Root joints (HAS_P=0) touch only the first quarter-chunk.
#define L1ROW(dst, p, HAS_P, r) do { \
    const ulonglong2* rw_ = (const ulonglong2*)(wj_ + (r)*8); \
    ulonglong2 q0_ = rw_[0]; \
    u64 acc_ = q0_.x; \
    acc_ = ffma2(q0_.y, in0_, acc_); \
    if (HAS_P) { \
        ulonglong2 q1_ = rw_[1], q2_ = rw_[2], q3_ = rw_[3]; \
        acc_ = ffma2(q1_.x, feat[p][0], acc_); \
        acc_ = ffma2(q1_.y, feat[p][1], acc_); \
        acc_ = ffma2(q2_.x, feat[p][2], acc_); \
        acc_ = ffma2(q2_.y, feat[p][3], acc_); \
        acc_ = ffma2(q3_.x, feat[p][4], acc_); \
        acc_ = ffma2(q3_.y, feat[p][5], acc_); \
    } \
    dst = relu2(acc_); \
} while (0)

// Layer-2 row r for joint j: chunk 7+r, writes feat + staging.
#define L2ROW(j, r) do { \
    const ulonglong2* rw_ = (const ulonglong2*)(wj_ + (7+(r))*8); \
    ulonglong2 q0_ = rw_[0], q1_ = rw_[1], q2_ = rw_[2], q3_ = rw_[3]; \
    u64 acc_ = q0_.x; \
    acc_ = ffma2(q0_.y, h0_, acc_); \
    acc_ = ffma2(q1_.x, h1_, acc_); \
    acc_ = ffma2(q1_.y, h2_, acc_); \
    acc_ = ffma2(q2_.x, h3_, acc_); \
    acc_ = ffma2(q2_.y, h4_, acc_); \
    acc_ = ffma2(q3_.x, h5_, acc_); \
    acc_ = ffma2(q3_.y, h6_, acc_); \
    u64 fv_ = relu2(acc_); \
    feat[j][r] = fv_; \
    float lo_, hi_; upk2(fv_, lo_, hi_); \
    s0[((j)&1)*6 + (r)] = lo_; \
    s1[((j)&1)*6 + (r)] = hi_; \
} while (0)

#define JOINT(j, HAS_P, p) do { \
    const u64* wj_ = sw + (j)*WPJ; \
    const u64 in0_ = xp[(j)&3]; \
    u64 h0_, h1_, h2_, h3_, h4_, h5_, h6_; \
    L1ROW(h0_, p, HAS_P, 0); L1ROW(h1_, p, HAS_P, 1); \
    L1ROW(h2_, p, HAS_P, 2); L1ROW(h3_, p, HAS_P, 3); \
    L1ROW(h4_, p, HAS_P, 4); L1ROW(h5_, p, HAS_P, 5); \
    L1ROW(h6_, p, HAS_P, 6); \
    L2ROW(j, 0); L2ROW(j, 1); L2ROW(j, 2); \
    L2ROW(j, 3); L2ROW(j, 4); L2ROW(j, 5); \
} while (0)

// Flush 2 joints (j-1, j) per output row as 3 aligned STG.128 each.
#define FLUSH(j) do { \
    const int base_ = ((j)-1)*6; \
    *(float4*)(o0+base_+0) = make_float4(s0[0], s0[1], s0[2],  s0[3]); \
    *(float4*)(o0+base_+4) = make_float4(s0[4], s0[5], s0[6],  s0[7]); \
    *(float4*)(o0+base_+8) = make_float4(s0[8], s0[9], s0[10], s0[11]); \
    *(float4*)(o1+base_+0) = make_float4(s1[0], s1[1], s1[2],  s1[3]); \
    *(float4*)(o1+base_+4) = make_float4(s1[4], s1[5], s1[6],  s1[7]); \
    *(float4*)(o1+base_+8) = make_float4(s1[8], s1[9], s1[10], s1[11]); \
} while (0)

    // Topological order 0..23 (PARENTS[i] < i), parents as literals.
    LOADX(0);
    JOINT(0, 0, 0);   JOINT(1, 1, 0);   FLUSH(1);
    JOINT(2, 1, 0);   JOINT(3, 1, 0);   FLUSH(3);
    LOADX(1);
    JOINT(4, 1, 1);   JOINT(5, 1, 2);   FLUSH(5);
    JOINT(6, 1, 3);   JOINT(7, 1, 4);   FLUSH(7);
    LOADX(2);
    JOINT(8, 1, 5);   JOINT(9, 1, 6);   FLUSH(9);
    JOINT(10, 1, 7);  JOINT(11, 1, 8);  FLUSH(11);
    LOADX(3);
    JOINT(12, 1, 9);  JOINT(13, 1, 9);  FLUSH(13);
    JOINT(14, 1, 9);  JOINT(15, 1, 12); FLUSH(15);
    LOADX(4);
    JOINT(16, 1, 13); JOINT(17, 1, 14); FLUSH(17);
    JOINT(18, 1, 16); JOINT(19, 1, 17); FLUSH(19);
    LOADX(5);
    JOINT(20, 1, 18); JOINT(21, 1, 19); FLUSH(21);
    JOINT(22, 1, 20); JOINT(23, 1, 21); FLUSH(23);
}

extern "C" void kernel_launch(void* const* d_in, const int* in_sizes, int n_in,
                              void* d_out, int out_size)
{
    const float* x  = (const float*)d_in[0];
    const float* W1 = (const float*)d_in[1];
    const float* b1 = (const float*)d_in[2];
    const float* W2 = (const float*)d_in[3];
    const float* b2 = (const float*)d_in[4];
    float* out = (float*)d_out;

    const int blocks = (PAIRS + TPB - 1) / TPB;
    se1d_kernel<<<blocks, TPB>>>(x, W1, b1, W2, b2, out);
}